// round 15
// baseline (speedup 1.0000x reference)
#include <cuda_runtime.h>
#include <cuda_fp16.h>

#define NG   2048
#define NB   4
#define CIN  16
#define COUT 32
#define NCTX 256
#define NOUT 1024

#define TPB   256
#define NWARP 8
#define RSTRIDE 2056            // fp16 elems per r row (2048 + 8 pad)
#define KSPLIT 8
#define KCHUNK (NG / KSPLIT)    // 256 grid points per warp
#define NITER (KCHUNK / 16)     // 16 MMA steps
#define ZROW  20                // padded z row (floats) for conflict-free STS
#define TGT_BLK 16              // targets per block

__device__ __forceinline__ float ex2(float x) {
    float y;
    asm("ex2.approx.ftz.f32 %0, %1;" : "=f"(y) : "f"(x));
    return y;
}
// result = {lo, hi}; PTX cvt.rn.f16x2.f32: first operand -> HIGH half.
__device__ __forceinline__ unsigned cvt_f16x2(float hi, float lo) {
    unsigned r;
    asm("cvt.rn.f16x2.f32 %0, %1, %2;" : "=r"(r) : "f"(hi), "f"(lo));
    return r;
}
__device__ __forceinline__ unsigned long long pack2(float lo, float hi) {
    unsigned long long v;
    asm("mov.b64 %0, {%1, %2};" : "=l"(v) : "f"(lo), "f"(hi));
    return v;
}
__device__ __forceinline__ void unpack2(unsigned long long v, float& lo, float& hi) {
    asm("mov.b64 {%0, %1}, %2;" : "=f"(lo), "=f"(hi) : "l"(v));
}
__device__ __forceinline__ void mul2(unsigned long long& d, unsigned long long a) {
    asm("mul.rn.f32x2 %0, %0, %1;" : "+l"(d) : "l"(a));
}
__device__ __forceinline__ void mma16816(float& d0, float& d1, float& d2, float& d3,
                                         unsigned a0, unsigned a1, unsigned a2, unsigned a3,
                                         unsigned b0, unsigned b1) {
    asm("mma.sync.aligned.m16n8k16.row.col.f32.f16.f16.f32 "
        "{%0,%1,%2,%3}, {%4,%5,%6,%7}, {%8,%9}, {%0,%1,%2,%3};"
        : "+f"(d0), "+f"(d1), "+f"(d2), "+f"(d3)
        : "r"(a0), "r"(a1), "r"(a2), "r"(a3), "r"(b0), "r"(b1));
}

extern __shared__ char smem_raw[];

__global__ __launch_bounds__(TPB, 2)
void conv_decoder_mma(const float* __restrict__ r,
                      const float* __restrict__ xc,
                      const float* __restrict__ xt,
                      const float* __restrict__ sigma,
                      const float* __restrict__ W,
                      const float* __restrict__ bias,
                      float* __restrict__ out) {
    __half* r_h   = (__half*)smem_raw;                       // [CIN][RSTRIDE]
    float*  W_s   = (float*)(smem_raw + CIN * RSTRIDE * 2);  // [CIN*COUT]
    float*  z_prt = W_s + CIN * COUT;                        // [KSPLIT][16][ZROW]

    __shared__ float s_mn[NWARP], s_mx[NWARP], s_sq[CIN];

    const int b    = blockIdx.y;
    const int tid  = threadIdx.x;
    const int warp = tid >> 5;
    const int lane = tid & 31;

    // Warp roles for the HMMA path (also used for prefetch below).
    const int ks  = warp;               // k-split 0..7
    const int i4  = lane & 3;
    const int grp = lane >> 2;
    const int g0  = ks * KCHUNK;

    // ---- Phase A: min/max scan, prescales, stage W and r(fp16) ----------
    {
        const float4* xc4 = (const float4*)xc;
        float4 v = xc4[tid];                         // 1024 = 256 float4
        float mn = fminf(fminf(v.x, v.y), fminf(v.z, v.w));
        float mx = fmaxf(fmaxf(v.x, v.y), fmaxf(v.z, v.w));
        const float4* xt4 = (const float4*)xt;
        #pragma unroll
        for (int j = 0; j < 4; j++) {                // 4096 = 1024 float4
            float4 t = xt4[j * TPB + tid];
            mn = fminf(mn, fminf(fminf(t.x, t.y), fminf(t.z, t.w)));
            mx = fmaxf(mx, fmaxf(fmaxf(t.x, t.y), fmaxf(t.z, t.w)));
        }
        #pragma unroll
        for (int s = 16; s > 0; s >>= 1) {
            mn = fminf(mn, __shfl_xor_sync(0xFFFFFFFFu, mn, s));
            mx = fmaxf(mx, __shfl_xor_sync(0xFFFFFFFFu, mx, s));
        }
        if (lane == 0) { s_mn[warp] = mn; s_mx[warp] = mx; }
    }
    if (tid < CIN) s_sq[tid] = 0.84932180028801907f * expf(-sigma[tid]);
    W_s[tid] = W[tid];
    W_s[tid + TPB] = W[tid + TPB];
    {
        // Warp stages channels {warp, warp+8}: 16 LDG.128 + STS each.
        #pragma unroll
        for (int h = 0; h < 2; h++) {
            int c = warp + h * 8;
            const float4* rb4 = (const float4*)(r + ((size_t)b * CIN + c) * NG);
            __half* dst = r_h + c * RSTRIDE;
            #pragma unroll
            for (int it = 0; it < 16; it++) {
                float4 v = rb4[it * 32 + lane];
                unsigned p0 = cvt_f16x2(v.y, v.x);
                unsigned p1 = cvt_f16x2(v.w, v.z);
                *(uint2*)(dst + it * 128 + lane * 4) = make_uint2(p0, p1);
            }
        }
    }

    // Prefetch target positions & bias BEFORE the barrier.
    const int o_r0 = blockIdx.x * TGT_BLK + grp;
    const float xr0 = xt[b * NOUT + o_r0];
    const float xr1 = xt[b * NOUT + o_r0 + 8];
    const float bv  = bias[lane];

    __syncthreads();

    float mn = (lane < NWARP) ? s_mn[lane] : 1e30f;
    float mx = (lane < NWARP) ? s_mx[lane] : -1e30f;
    #pragma unroll
    for (int s = 16; s > 0; s >>= 1) {
        mn = fminf(mn, __shfl_xor_sync(0xFFFFFFFFu, mn, s));
        mx = fmaxf(mx, __shfl_xor_sync(0xFFFFFFFFu, mx, s));
    }
    const float xmin = mn - 0.1f;
    const float step = (mx + 0.1f - xmin) / (float)(NG - 1);

    bool uniform = true;
    #pragma unroll
    for (int c = 1; c < CIN; c++) uniform &= (s_sq[c] == s_sq[0]);

    if (uniform) {
        // ---- HMMA: z(16x16) = wt(16x2048) @ rT(2048x16) ------------------
        const float sq    = s_sq[0];
        const float stepq = step * sq;
        const float xminq = xmin * sq;
        const float S     = 16.0f * stepq;          // scaled k-step stride
        const float qs    = ex2(-2.0f * S * S);
        const unsigned long long qq = pack2(qs, qs);

        const float xq0 = xr0 * sq;
        const float xq1 = xr1 * sq;

        // Packed weight/update pairs: pw[rr][p] = {w(col_p), w(col_p+1)},
        // col_0 = 2*i4, col_1 = 2*i4+8.
        unsigned long long pw[2][2], pu[2][2];
        #pragma unroll
        for (int p = 0; p < 2; p++) {
            float col = (float)(2 * i4 + 8 * p);
            float pos0 = fmaf((float)g0 + col, stepq, xminq);
            float pos1 = pos0 + stepq;
            float dA0 = pos0 - xq0, dA1 = pos1 - xq0;
            float dB0 = pos0 - xq1, dB1 = pos1 - xq1;
            pw[0][p] = pack2(ex2(-dA0 * dA0), ex2(-dA1 * dA1));
            pw[1][p] = pack2(ex2(-dB0 * dB0), ex2(-dB1 * dB1));
            pu[0][p] = pack2(ex2(-S * (2.0f * dA0 + S)), ex2(-S * (2.0f * dA1 + S)));
            pu[1][p] = pack2(ex2(-S * (2.0f * dB0 + S)), ex2(-S * (2.0f * dB1 + S)));
        }

        const __half* bp0 = r_h + grp * RSTRIDE + g0 + 2 * i4;        // ch 0-7
        const __half* bp1 = bp0 + 8 * RSTRIDE;                        // ch 8-15
        float c0 = 0.f, c1 = 0.f, c2 = 0.f, c3 = 0.f;
        float c4 = 0.f, c5 = 0.f, c6 = 0.f, c7 = 0.f;

        #pragma unroll 1
        for (int j = 0; j < NITER; j++) {
            float lo, hi;
            unpack2(pw[0][0], lo, hi); unsigned A0 = cvt_f16x2(hi, lo);
            unpack2(pw[1][0], lo, hi); unsigned A1 = cvt_f16x2(hi, lo);
            unpack2(pw[0][1], lo, hi); unsigned A2 = cvt_f16x2(hi, lo);
            unpack2(pw[1][1], lo, hi); unsigned A3 = cvt_f16x2(hi, lo);

            unsigned B00 = *(const unsigned*)bp0;
            unsigned B01 = *(const unsigned*)(bp0 + 8);
            unsigned B10 = *(const unsigned*)bp1;
            unsigned B11 = *(const unsigned*)(bp1 + 8);
            bp0 += 16; bp1 += 16;

            mma16816(c0, c1, c2, c3, A0, A1, A2, A3, B00, B01);
            mma16816(c4, c5, c6, c7, A0, A1, A2, A3, B10, B11);

            #pragma unroll
            for (int rr = 0; rr < 2; rr++)
                #pragma unroll
                for (int p = 0; p < 2; p++) {
                    mul2(pw[rr][p], pu[rr][p]);
                    mul2(pu[rr][p], qq);
                }
        }

        // Scatter 16x16 partial into this warp's k-split slot (float2 STS).
        {
            float* zp = z_prt + ks * (TGT_BLK * ZROW);
            *(float2*)(zp + grp * ZROW + 2 * i4)           = make_float2(c0, c1);
            *(float2*)(zp + (grp + 8) * ZROW + 2 * i4)     = make_float2(c2, c3);
            *(float2*)(zp + grp * ZROW + 8 + 2 * i4)       = make_float2(c4, c5);
            *(float2*)(zp + (grp + 8) * ZROW + 8 + 2 * i4) = make_float2(c6, c7);
        }
        __syncthreads();

        // Merged combine + projection: warp owns rows {2w, 2w+1};
        // lane -> (rr = lane>>4, cc = lane&15).
        {
            const int rr = lane >> 4;
            const int cc = lane & 15;
            const int row = warp * 2 + rr;
            float zsum = 0.f;
            #pragma unroll
            for (int k = 0; k < KSPLIT; k++)
                zsum += z_prt[k * (TGT_BLK * ZROW) + row * ZROW + cc];

            float o0 = bv, o1 = bv;
            #pragma unroll
            for (int c = 0; c < CIN; c++) {
                float z0 = __shfl_sync(0xFFFFFFFFu, zsum, c);
                float z1 = __shfl_sync(0xFFFFFFFFu, zsum, 16 + c);
                float w = W_s[c * COUT + lane];
                o0 = fmaf(z0, w, o0);
                o1 = fmaf(z1, w, o1);
            }
            size_t obase = ((size_t)b * NOUT + blockIdx.x * TGT_BLK + warp * 2) * COUT + lane;
            out[obase]        = o0;
            out[obase + COUT] = o1;
        }
    } else {
        // ---- Cold path: per-channel length scales (correctness only) -----
        float kneg[CIN];
        #pragma unroll
        for (int c = 0; c < CIN; c++) { float s = s_sq[c]; kneg[c] = -(s * s); }

        int o0 = blockIdx.x * TGT_BLK + warp * 2;
        float xv0 = xt[b * NOUT + o0];
        float xv1 = xt[b * NOUT + o0 + 1];
        float a0[CIN], a1[CIN];
        #pragma unroll
        for (int c = 0; c < CIN; c++) { a0[c] = 0.f; a1[c] = 0.f; }

        const float* rb = r + (size_t)b * CIN * NG;
        #pragma unroll 1
        for (int g = lane; g < NG; g += 32) {
            float gv = fmaf((float)g, step, xmin);
            float dd0 = gv - xv0, dd1 = gv - xv1;
            float d20 = dd0 * dd0, d21 = dd1 * dd1;
            #pragma unroll
            for (int c = 0; c < CIN; c++) {
                float rv = rb[c * NG + g];
                a0[c] = fmaf(rv, ex2(d20 * kneg[c]), a0[c]);
                a1[c] = fmaf(rv, ex2(d21 * kneg[c]), a1[c]);
            }
        }
        #pragma unroll
        for (int s = 16; s > 0; s >>= 1)
            #pragma unroll
            for (int c = 0; c < CIN; c++) {
                a0[c] += __shfl_xor_sync(0xFFFFFFFFu, a0[c], s);
                a1[c] += __shfl_xor_sync(0xFFFFFFFFu, a1[c], s);
            }
        float o0v = bv, o1v = bv;
        #pragma unroll
        for (int c = 0; c < CIN; c++) {
            o0v = fmaf(a0[c], W_s[c * COUT + lane], o0v);
            o1v = fmaf(a1[c], W_s[c * COUT + lane], o1v);
        }
        out[((size_t)b * NOUT + o0 + 0) * COUT + lane] = o0v;
        out[((size_t)b * NOUT + o0 + 1) * COUT + lane] = o1v;
    }
}

extern "C" void kernel_launch(void* const* d_in, const int* in_sizes, int n_in,
                              void* d_out, int out_size) {
    const float* r     = (const float*)d_in[0];
    const float* xc    = (const float*)d_in[1];
    // d_in[2] = y_context — unused by the reference computation.
    const float* xt    = (const float*)d_in[3];
    const float* sigma = (const float*)d_in[4];
    const float* W     = (const float*)d_in[5];
    const float* bias  = (const float*)d_in[6];
    float* out = (float*)d_out;

    (void)in_sizes; (void)n_in; (void)out_size;

    const int smem_bytes = CIN * RSTRIDE * 2               // r fp16 (65.8 KB)
                         + CIN * COUT * 4                  // W (2 KB)
                         + KSPLIT * TGT_BLK * ZROW * 4;    // z partials (10.2 KB)
    cudaFuncSetAttribute(conv_decoder_mma,
                         cudaFuncAttributeMaxDynamicSharedMemorySize, smem_bytes);

    dim3 grid(NOUT / TGT_BLK, NB);   // (64, 4) = 256 blocks, 2 per SM
    conv_decoder_mma<<<grid, TPB, smem_bytes>>>(r, xc, xt, sigma, W, bias, out);
}

// round 16
// speedup vs baseline: 1.0469x; 1.0469x over previous
#include <cuda_runtime.h>
#include <cuda_fp16.h>

#define NG   2048
#define NB   4
#define CIN  16
#define COUT 32
#define NCTX 256
#define NOUT 1024

#define TPB   512
#define NWARP 16
#define KSPLIT 8
#define KCHUNK (NG / KSPLIT)    // 256 grid points per k-split
#define NITER (KCHUNK / 16)     // 16 MMA steps
#define ZROW  20                // padded z row (floats)
#define FROW  264               // fp32 elems per channel row in smem (256 + 8 pad)
#define FREG  (CIN * FROW)      // floats per k-split region (4224)

__device__ __forceinline__ float ex2(float x) {
    float y;
    asm("ex2.approx.ftz.f32 %0, %1;" : "=f"(y) : "f"(x));
    return y;
}
// result = {lo, hi}; PTX cvt.rn.f16x2.f32: first operand -> HIGH half.
__device__ __forceinline__ unsigned cvt_f16x2(float hi, float lo) {
    unsigned r;
    asm("cvt.rn.f16x2.f32 %0, %1, %2;" : "=r"(r) : "f"(hi), "f"(lo));
    return r;
}
__device__ __forceinline__ unsigned long long pack2(float lo, float hi) {
    unsigned long long v;
    asm("mov.b64 %0, {%1, %2};" : "=l"(v) : "f"(lo), "f"(hi));
    return v;
}
__device__ __forceinline__ void unpack2(unsigned long long v, float& lo, float& hi) {
    asm("mov.b64 {%0, %1}, %2;" : "=f"(lo), "=f"(hi) : "l"(v));
}
__device__ __forceinline__ void mul2(unsigned long long& d, unsigned long long a) {
    asm("mul.rn.f32x2 %0, %0, %1;" : "+l"(d) : "l"(a));
}
__device__ __forceinline__ void cp_async16(unsigned dst, const void* src) {
    asm volatile("cp.async.ca.shared.global [%0], [%1], 16;"
                 :: "r"(dst), "l"(src) : "memory");
}
__device__ __forceinline__ void mma16816(float& d0, float& d1, float& d2, float& d3,
                                         unsigned a0, unsigned a1, unsigned a2, unsigned a3,
                                         unsigned b0, unsigned b1) {
    asm("mma.sync.aligned.m16n8k16.row.col.f32.f16.f16.f32 "
        "{%0,%1,%2,%3}, {%4,%5,%6,%7}, {%8,%9}, {%0,%1,%2,%3};"
        : "+f"(d0), "+f"(d1), "+f"(d2), "+f"(d3)
        : "r"(a0), "r"(a1), "r"(a2), "r"(a3), "r"(b0), "r"(b1));
}

extern __shared__ char smem_raw[];

__global__ __launch_bounds__(TPB, 1)
void conv_decoder_mma(const float* __restrict__ r,
                      const float* __restrict__ xc,
                      const float* __restrict__ xt,
                      const float* __restrict__ sigma,
                      const float* __restrict__ W,
                      const float* __restrict__ bias,
                      float* __restrict__ out) {
    float* r_f   = (float*)smem_raw;                 // [KSPLIT][CIN][FROW] fp32
    float* W_s   = r_f + KSPLIT * FREG;              // [CIN*COUT]
    float* z_prt = W_s + CIN * COUT;                 // [KSPLIT][32][ZROW]

    __shared__ float s_mn[NWARP], s_mx[NWARP], s_sq[CIN];

    const int b    = blockIdx.y;
    const int tid  = threadIdx.x;
    const int warp = tid >> 5;
    const int lane = tid & 31;

    const int mt  = warp & 1;           // m-tile (16 targets)
    const int ks  = warp >> 1;          // k-split 0..7
    const int i4  = lane & 3;
    const int grp = lane >> 2;
    const int g0  = ks * KCHUNK;

    // ---- Phase A: min/max scan + cp.async staging (fp32, no registers) ---
    {
        float mn = fminf(xc[tid], xc[tid + 512]);
        float mx = fmaxf(xc[tid], xc[tid + 512]);
        const float4* xt4 = (const float4*)xt;
        #pragma unroll
        for (int j = 0; j < 2; j++) {
            float4 v = xt4[j * 512 + tid];
            mn = fminf(mn, fminf(fminf(v.x, v.y), fminf(v.z, v.w)));
            mx = fmaxf(mx, fmaxf(fmaxf(v.x, v.y), fmaxf(v.z, v.w)));
        }
        #pragma unroll
        for (int s = 16; s > 0; s >>= 1) {
            mn = fminf(mn, __shfl_xor_sync(0xFFFFFFFFu, mn, s));
            mx = fmaxf(mx, __shfl_xor_sync(0xFFFFFFFFu, mx, s));
        }
        if (lane == 0) { s_mn[warp] = mn; s_mx[warp] = mx; }
    }
    if (tid < CIN) s_sq[tid] = 0.84932180028801907f * expf(-sigma[tid]);
    W_s[tid] = W[tid];                       // CIN*COUT == 512 == TPB

    // Staging: warp (mt, ks) copies channels [mt*8, mt*8+8) of grid chunk
    // [g0, g0+256) into the pair's region. 16 cp.async.16B per thread.
    {
        unsigned rbase;
        {
            unsigned long long gp = __cvta_generic_to_shared(r_f + ks * FREG);
            rbase = (unsigned)gp;
        }
        const float* rb = r + (size_t)b * CIN * NG + g0 + lane * 4;
        #pragma unroll
        for (int cc = 0; cc < 8; cc++) {
            int c = mt * 8 + cc;
            unsigned d0 = rbase + (unsigned)(c * FROW + lane * 4) * 4u;
            const float* s0 = rb + (size_t)c * NG;
            cp_async16(d0, s0);
            cp_async16(d0 + 128 * 4, s0 + 128);
        }
        asm volatile("cp.async.commit_group;" ::: "memory");
    }

    // Prefetch target positions & bias while copies are in flight.
    const int o_r0 = blockIdx.x * 32 + mt * 16 + grp;
    const float xr0 = xt[b * NOUT + o_r0];
    const float xr1 = xt[b * NOUT + o_r0 + 8];
    const float bv  = bias[lane];

    asm volatile("cp.async.wait_group 0;" ::: "memory");
    __syncthreads();

    float mn = (lane < NWARP) ? s_mn[lane] : 1e30f;
    float mx = (lane < NWARP) ? s_mx[lane] : -1e30f;
    #pragma unroll
    for (int s = 16; s > 0; s >>= 1) {
        mn = fminf(mn, __shfl_xor_sync(0xFFFFFFFFu, mn, s));
        mx = fmaxf(mx, __shfl_xor_sync(0xFFFFFFFFu, mx, s));
    }
    const float xmin = mn - 0.1f;
    const float step = (mx + 0.1f - xmin) / (float)(NG - 1);

    bool uniform = true;
    #pragma unroll
    for (int c = 1; c < CIN; c++) uniform &= (s_sq[c] == s_sq[0]);

    if (uniform) {
        // ---- HMMA: z(32x16) = wt(32x2048) @ rT(2048x16) ------------------
        const float sq    = s_sq[0];
        const float stepq = step * sq;
        const float xminq = xmin * sq;
        const float S     = 16.0f * stepq;          // scaled k-step stride
        const float qs    = ex2(-2.0f * S * S);
        const unsigned long long qq = pack2(qs, qs);

        const float xq0 = xr0 * sq;
        const float xq1 = xr1 * sq;

        // Packed weight/update pairs: pw[rr][p] = {w(col_p), w(col_p+1)},
        // col_0 = 2*i4, col_1 = 2*i4+8.
        unsigned long long pw[2][2], pu[2][2];
        #pragma unroll
        for (int p = 0; p < 2; p++) {
            float col = (float)(2 * i4 + 8 * p);
            float pos0 = fmaf((float)g0 + col, stepq, xminq);
            float pos1 = pos0 + stepq;
            float dA0 = pos0 - xq0, dA1 = pos1 - xq0;
            float dB0 = pos0 - xq1, dB1 = pos1 - xq1;
            pw[0][p] = pack2(ex2(-dA0 * dA0), ex2(-dA1 * dA1));
            pw[1][p] = pack2(ex2(-dB0 * dB0), ex2(-dB1 * dB1));
            pu[0][p] = pack2(ex2(-S * (2.0f * dA0 + S)), ex2(-S * (2.0f * dA1 + S)));
            pu[1][p] = pack2(ex2(-S * (2.0f * dB0 + S)), ex2(-S * (2.0f * dB1 + S)));
        }

        // B from fp32 smem: row = channel, stride FROW (conflict-free LDS.64).
        const float* bq0 = r_f + ks * FREG + grp * FROW + 2 * i4;   // ch 0-7
        const float* bq1 = bq0 + 8 * FROW;                          // ch 8-15
        float c0 = 0.f, c1 = 0.f, c2 = 0.f, c3 = 0.f;
        float c4 = 0.f, c5 = 0.f, c6 = 0.f, c7 = 0.f;

        #pragma unroll 1
        for (int j = 0; j < NITER; j++) {
            float lo, hi;
            unpack2(pw[0][0], lo, hi); unsigned A0 = cvt_f16x2(hi, lo);
            unpack2(pw[1][0], lo, hi); unsigned A1 = cvt_f16x2(hi, lo);
            unpack2(pw[0][1], lo, hi); unsigned A2 = cvt_f16x2(hi, lo);
            unpack2(pw[1][1], lo, hi); unsigned A3 = cvt_f16x2(hi, lo);

            float2 x00 = *(const float2*)bq0;
            float2 x01 = *(const float2*)(bq0 + 8);
            float2 x10 = *(const float2*)bq1;
            float2 x11 = *(const float2*)(bq1 + 8);
            bq0 += 16; bq1 += 16;
            unsigned B00 = cvt_f16x2(x00.y, x00.x);
            unsigned B01 = cvt_f16x2(x01.y, x01.x);
            unsigned B10 = cvt_f16x2(x10.y, x10.x);
            unsigned B11 = cvt_f16x2(x11.y, x11.x);

            mma16816(c0, c1, c2, c3, A0, A1, A2, A3, B00, B01);
            mma16816(c4, c5, c6, c7, A0, A1, A2, A3, B10, B11);

            #pragma unroll
            for (int rr = 0; rr < 2; rr++)
                #pragma unroll
                for (int p = 0; p < 2; p++) {
                    mul2(pw[rr][p], pu[rr][p]);
                    mul2(pu[rr][p], qq);
                }
        }

        // Scatter 16x16 partial into this warp's k-split slot (float2 STS).
        {
            float* zp = z_prt + ks * (32 * ZROW) + (mt * 16) * ZROW;
            *(float2*)(zp + grp * ZROW + 2 * i4)           = make_float2(c0, c1);
            *(float2*)(zp + (grp + 8) * ZROW + 2 * i4)     = make_float2(c2, c3);
            *(float2*)(zp + grp * ZROW + 8 + 2 * i4)       = make_float2(c4, c5);
            *(float2*)(zp + (grp + 8) * ZROW + 8 + 2 * i4) = make_float2(c6, c7);
        }
        __syncthreads();

        // Merged combine + projection: warp owns rows {2w, 2w+1};
        // lane -> (rr = lane>>4, cc = lane&15).
        {
            const int rr = lane >> 4;
            const int cc = lane & 15;
            const int row = warp * 2 + rr;
            float zsum = 0.f;
            #pragma unroll
            for (int k = 0; k < KSPLIT; k++)
                zsum += z_prt[k * (32 * ZROW) + row * ZROW + cc];

            float o0 = bv, o1 = bv;
            #pragma unroll
            for (int c = 0; c < CIN; c++) {
                float z0 = __shfl_sync(0xFFFFFFFFu, zsum, c);
                float z1 = __shfl_sync(0xFFFFFFFFu, zsum, 16 + c);
                float w = W_s[c * COUT + lane];
                o0 = fmaf(z0, w, o0);
                o1 = fmaf(z1, w, o1);
            }
            size_t obase = ((size_t)b * NOUT + blockIdx.x * 32 + warp * 2) * COUT + lane;
            out[obase]        = o0;
            out[obase + COUT] = o1;
        }
    } else {
        // ---- Cold path: per-channel length scales (correctness only) -----
        float kneg[CIN];
        #pragma unroll
        for (int c = 0; c < CIN; c++) { float s = s_sq[c]; kneg[c] = -(s * s); }

        int o0 = blockIdx.x * 32 + warp * 2;
        float xv0 = xt[b * NOUT + o0];
        float xv1 = xt[b * NOUT + o0 + 1];
        float a0[CIN], a1[CIN];
        #pragma unroll
        for (int c = 0; c < CIN; c++) { a0[c] = 0.f; a1[c] = 0.f; }

        const float* rb = r + (size_t)b * CIN * NG;
        #pragma unroll 1
        for (int g = lane; g < NG; g += 32) {
            float gv = fmaf((float)g, step, xmin);
            float dd0 = gv - xv0, dd1 = gv - xv1;
            float d20 = dd0 * dd0, d21 = dd1 * dd1;
            #pragma unroll
            for (int c = 0; c < CIN; c++) {
                float rv = rb[c * NG + g];
                a0[c] = fmaf(rv, ex2(d20 * kneg[c]), a0[c]);
                a1[c] = fmaf(rv, ex2(d21 * kneg[c]), a1[c]);
            }
        }
        #pragma unroll
        for (int s = 16; s > 0; s >>= 1)
            #pragma unroll
            for (int c = 0; c < CIN; c++) {
                a0[c] += __shfl_xor_sync(0xFFFFFFFFu, a0[c], s);
                a1[c] += __shfl_xor_sync(0xFFFFFFFFu, a1[c], s);
            }
        float o0v = bv, o1v = bv;
        #pragma unroll
        for (int c = 0; c < CIN; c++) {
            o0v = fmaf(a0[c], W_s[c * COUT + lane], o0v);
            o1v = fmaf(a1[c], W_s[c * COUT + lane], o1v);
        }
        out[((size_t)b * NOUT + o0 + 0) * COUT + lane] = o0v;
        out[((size_t)b * NOUT + o0 + 1) * COUT + lane] = o1v;
    }
}

extern "C" void kernel_launch(void* const* d_in, const int* in_sizes, int n_in,
                              void* d_out, int out_size) {
    const float* r     = (const float*)d_in[0];
    const float* xc    = (const float*)d_in[1];
    // d_in[2] = y_context — unused by the reference computation.
    const float* xt    = (const float*)d_in[3];
    const float* sigma = (const float*)d_in[4];
    const float* W     = (const float*)d_in[5];
    const float* bias  = (const float*)d_in[6];
    float* out = (float*)d_out;

    (void)in_sizes; (void)n_in; (void)out_size;

    const int smem_bytes = KSPLIT * FREG * 4          // r fp32 (135.2 KB)
                         + CIN * COUT * 4             // W (2 KB)
                         + KSPLIT * 32 * ZROW * 4;    // z partials (20.5 KB)
    cudaFuncSetAttribute(conv_decoder_mma,
                         cudaFuncAttributeMaxDynamicSharedMemorySize, smem_bytes);

    dim3 grid(NOUT / 32, NB);   // (32, 4) = 128 blocks, 1 per SM
    conv_decoder_mma<<<grid, TPB, smem_bytes>>>(r, xc, xt, sigma, W, bias, out);
}

// round 17
// speedup vs baseline: 1.1552x; 1.1034x over previous
#include <cuda_runtime.h>
#include <cuda_fp16.h>

#define NG   2048
#define NB   4
#define CIN  16
#define COUT 32
#define NCTX 256
#define NOUT 1024

#define TPB   512
#define NWARP 16
#define KSPLIT 16
#define KCHUNK (NG / KSPLIT)    // 128 grid points per warp
#define NITER (KCHUNK / 16)     // 8 MMA steps
#define ZROW  20                // padded z row (floats)
#define FROW  136               // fp32 elems per channel row (128 + 8 pad)
#define FREG  (CIN * FROW)      // floats per k-split region (2176)

__device__ __forceinline__ float ex2(float x) {
    float y;
    asm("ex2.approx.ftz.f32 %0, %1;" : "=f"(y) : "f"(x));
    return y;
}
// result = {lo, hi}; PTX cvt.rn.f16x2.f32: first operand -> HIGH half.
__device__ __forceinline__ unsigned cvt_f16x2(float hi, float lo) {
    unsigned r;
    asm("cvt.rn.f16x2.f32 %0, %1, %2;" : "=r"(r) : "f"(hi), "f"(lo));
    return r;
}
__device__ __forceinline__ unsigned long long pack2(float lo, float hi) {
    unsigned long long v;
    asm("mov.b64 %0, {%1, %2};" : "=l"(v) : "f"(lo), "f"(hi));
    return v;
}
__device__ __forceinline__ void unpack2(unsigned long long v, float& lo, float& hi) {
    asm("mov.b64 {%0, %1}, %2;" : "=f"(lo), "=f"(hi) : "l"(v));
}
__device__ __forceinline__ void mul2(unsigned long long& d, unsigned long long a) {
    asm("mul.rn.f32x2 %0, %0, %1;" : "+l"(d) : "l"(a));
}
__device__ __forceinline__ void cp_async16(unsigned dst, const void* src) {
    asm volatile("cp.async.ca.shared.global [%0], [%1], 16;"
                 :: "r"(dst), "l"(src) : "memory");
}
__device__ __forceinline__ void mma16816(float* d,
                                         unsigned a0, unsigned a1, unsigned a2, unsigned a3,
                                         unsigned b0, unsigned b1) {
    asm("mma.sync.aligned.m16n8k16.row.col.f32.f16.f16.f32 "
        "{%0,%1,%2,%3}, {%4,%5,%6,%7}, {%8,%9}, {%0,%1,%2,%3};"
        : "+f"(d[0]), "+f"(d[1]), "+f"(d[2]), "+f"(d[3])
        : "r"(a0), "r"(a1), "r"(a2), "r"(a3), "r"(b0), "r"(b1));
}

extern __shared__ char smem_raw[];

__global__ __launch_bounds__(TPB, 1)
void conv_decoder_mma(const float* __restrict__ r,
                      const float* __restrict__ xc,
                      const float* __restrict__ xt,
                      const float* __restrict__ sigma,
                      const float* __restrict__ W,
                      const float* __restrict__ bias,
                      float* __restrict__ out) {
    float* r_f   = (float*)smem_raw;                 // [KSPLIT][CIN][FROW] fp32
    float* W_s   = r_f + KSPLIT * FREG;              // [CIN*COUT]
    float* z_prt = W_s + CIN * COUT;                 // [KSPLIT][32][ZROW]

    __shared__ float s_mn[NWARP], s_mx[NWARP], s_sq[CIN];

    const int b    = blockIdx.y;
    const int tid  = threadIdx.x;
    const int warp = tid >> 5;
    const int lane = tid & 31;

    const int ks  = warp;               // k-split 0..15
    const int i4  = lane & 3;
    const int grp = lane >> 2;
    const int g0  = ks * KCHUNK;

    // ---- 1. Fire this warp's OWN staging copies first (fp32, 16/thread) --
    {
        unsigned rbase = (unsigned)__cvta_generic_to_shared(r_f + ks * FREG);
        const float* rb = r + (size_t)b * CIN * NG + g0 + lane * 4;
        #pragma unroll
        for (int c = 0; c < CIN; c++)
            cp_async16(rbase + (unsigned)(c * FROW + lane * 4) * 4u,
                       rb + (size_t)c * NG);
        asm volatile("cp.async.commit_group;" ::: "memory");
    }

    // ---- 2. min/max scan + prescales + W (overlaps the copies) -----------
    {
        float mn = fminf(xc[tid], xc[tid + 512]);
        float mx = fmaxf(xc[tid], xc[tid + 512]);
        const float4* xt4 = (const float4*)xt;
        #pragma unroll
        for (int j = 0; j < 2; j++) {
            float4 v = xt4[j * 512 + tid];
            mn = fminf(mn, fminf(fminf(v.x, v.y), fminf(v.z, v.w)));
            mx = fmaxf(mx, fmaxf(fmaxf(v.x, v.y), fmaxf(v.z, v.w)));
        }
        #pragma unroll
        for (int s = 16; s > 0; s >>= 1) {
            mn = fminf(mn, __shfl_xor_sync(0xFFFFFFFFu, mn, s));
            mx = fmaxf(mx, __shfl_xor_sync(0xFFFFFFFFu, mx, s));
        }
        if (lane == 0) { s_mn[warp] = mn; s_mx[warp] = mx; }
    }
    if (tid < CIN) s_sq[tid] = 0.84932180028801907f * expf(-sigma[tid]);
    W_s[tid] = W[tid];

    // Prefetch the 4 target rows this warp owns + bias.
    const int orow = blockIdx.x * 32 + grp;
    const float xr00 = xt[b * NOUT + orow];          // mtile0 row grp
    const float xr01 = xt[b * NOUT + orow + 8];      // mtile0 row grp+8
    const float xr10 = xt[b * NOUT + orow + 16];     // mtile1 row grp
    const float xr11 = xt[b * NOUT + orow + 24];     // mtile1 row grp+8
    const float bv   = bias[lane];

    // Cheap block barrier: only orders the 1 KB min/max + s_sq exchange.
    // Does NOT wait on the async copies.
    __syncthreads();

    float mn = (lane < NWARP) ? s_mn[lane] : 1e30f;
    float mx = (lane < NWARP) ? s_mx[lane] : -1e30f;
    #pragma unroll
    for (int s = 16; s > 0; s >>= 1) {
        mn = fminf(mn, __shfl_xor_sync(0xFFFFFFFFu, mn, s));
        mx = fmaxf(mx, __shfl_xor_sync(0xFFFFFFFFu, mx, s));
    }
    const float xmin = mn - 0.1f;
    const float step = (mx + 0.1f - xmin) / (float)(NG - 1);

    bool uniform = true;
    #pragma unroll
    for (int c = 1; c < CIN; c++) uniform &= (s_sq[c] == s_sq[0]);

    if (uniform) {
        // ---- HMMA: warp owns all 32 targets x its 128-pt k-chunk ---------
        const float sq    = s_sq[0];
        const float stepq = step * sq;
        const float xminq = xmin * sq;
        const float S     = 16.0f * stepq;
        const float qs    = ex2(-2.0f * S * S);
        const unsigned long long qq = pack2(qs, qs);

        const float xq[2][2] = { { xr00 * sq, xr01 * sq },
                                 { xr10 * sq, xr11 * sq } };

        // pw[mt][rr][p] = packed {w(col_p), w(col_p+1)}, col_p = 2*i4 + 8p.
        unsigned long long pw[2][2][2], pu[2][2][2];
        #pragma unroll
        for (int mt = 0; mt < 2; mt++)
            #pragma unroll
            for (int p = 0; p < 2; p++) {
                float col = (float)(2 * i4 + 8 * p);
                float pos0 = fmaf((float)g0 + col, stepq, xminq);
                float pos1 = pos0 + stepq;
                #pragma unroll
                for (int rr = 0; rr < 2; rr++) {
                    float d0 = pos0 - xq[mt][rr];
                    float d1 = pos1 - xq[mt][rr];
                    pw[mt][rr][p] = pack2(ex2(-d0 * d0), ex2(-d1 * d1));
                    pu[mt][rr][p] = pack2(ex2(-S * (2.0f * d0 + S)),
                                          ex2(-S * (2.0f * d1 + S)));
                }
            }

        // Wait ONLY for this warp's own copies; warp-local visibility.
        asm volatile("cp.async.wait_group 0;" ::: "memory");
        __syncwarp();

        const float* bq0 = r_f + ks * FREG + grp * FROW + 2 * i4;   // ch 0-7
        const float* bq1 = bq0 + 8 * FROW;                          // ch 8-15
        float acc[2][2][4];
        #pragma unroll
        for (int mt = 0; mt < 2; mt++)
            #pragma unroll
            for (int nt = 0; nt < 2; nt++)
                #pragma unroll
                for (int k = 0; k < 4; k++) acc[mt][nt][k] = 0.f;

        #pragma unroll 1
        for (int j = 0; j < NITER; j++) {
            unsigned A[2][4];
            #pragma unroll
            for (int mt = 0; mt < 2; mt++) {
                float lo, hi;
                unpack2(pw[mt][0][0], lo, hi); A[mt][0] = cvt_f16x2(hi, lo);
                unpack2(pw[mt][1][0], lo, hi); A[mt][1] = cvt_f16x2(hi, lo);
                unpack2(pw[mt][0][1], lo, hi); A[mt][2] = cvt_f16x2(hi, lo);
                unpack2(pw[mt][1][1], lo, hi); A[mt][3] = cvt_f16x2(hi, lo);
            }
            float2 x00 = *(const float2*)bq0;
            float2 x01 = *(const float2*)(bq0 + 8);
            float2 x10 = *(const float2*)bq1;
            float2 x11 = *(const float2*)(bq1 + 8);
            bq0 += 16; bq1 += 16;
            unsigned B00 = cvt_f16x2(x00.y, x00.x);
            unsigned B01 = cvt_f16x2(x01.y, x01.x);
            unsigned B10 = cvt_f16x2(x10.y, x10.x);
            unsigned B11 = cvt_f16x2(x11.y, x11.x);

            #pragma unroll
            for (int mt = 0; mt < 2; mt++) {
                mma16816(acc[mt][0], A[mt][0], A[mt][1], A[mt][2], A[mt][3], B00, B01);
                mma16816(acc[mt][1], A[mt][0], A[mt][1], A[mt][2], A[mt][3], B10, B11);
            }
            #pragma unroll
            for (int mt = 0; mt < 2; mt++)
                #pragma unroll
                for (int rr = 0; rr < 2; rr++)
                    #pragma unroll
                    for (int p = 0; p < 2; p++) {
                        mul2(pw[mt][rr][p], pu[mt][rr][p]);
                        mul2(pu[mt][rr][p], qq);
                    }
        }

        // Scatter 32x16 partial into this warp's k-split slot.
        {
            float* zp = z_prt + ks * (32 * ZROW);
            #pragma unroll
            for (int mt = 0; mt < 2; mt++)
                #pragma unroll
                for (int nt = 0; nt < 2; nt++) {
                    float* q = zp + (mt * 16) * ZROW + nt * 8 + 2 * i4;
                    *(float2*)(q + grp * ZROW)       = make_float2(acc[mt][nt][0], acc[mt][nt][1]);
                    *(float2*)(q + (grp + 8) * ZROW) = make_float2(acc[mt][nt][2], acc[mt][nt][3]);
                }
        }
        __syncthreads();

        // Merged combine + projection: warp owns rows {2w, 2w+1};
        // lane -> (rr = lane>>4, cc = lane&15).
        {
            const int rr = lane >> 4;
            const int cc = lane & 15;
            const int row = warp * 2 + rr;
            float zsum = 0.f;
            #pragma unroll
            for (int k = 0; k < KSPLIT; k++)
                zsum += z_prt[k * (32 * ZROW) + row * ZROW + cc];

            float o0 = bv, o1 = bv;
            #pragma unroll
            for (int c = 0; c < CIN; c++) {
                float z0 = __shfl_sync(0xFFFFFFFFu, zsum, c);
                float z1 = __shfl_sync(0xFFFFFFFFu, zsum, 16 + c);
                float w = W_s[c * COUT + lane];
                o0 = fmaf(z0, w, o0);
                o1 = fmaf(z1, w, o1);
            }
            size_t obase = ((size_t)b * NOUT + blockIdx.x * 32 + warp * 2) * COUT + lane;
            out[obase]        = o0;
            out[obase + COUT] = o1;
        }
    } else {
        // ---- Cold path: per-channel length scales (reads global r) -------
        asm volatile("cp.async.wait_group 0;" ::: "memory");
        float kneg[CIN];
        #pragma unroll
        for (int c = 0; c < CIN; c++) { float s = s_sq[c]; kneg[c] = -(s * s); }

        int o0 = blockIdx.x * 32 + warp * 2;
        float xv0 = xt[b * NOUT + o0];
        float xv1 = xt[b * NOUT + o0 + 1];
        float a0[CIN], a1[CIN];
        #pragma unroll
        for (int c = 0; c < CIN; c++) { a0[c] = 0.f; a1[c] = 0.f; }

        const float* rb = r + (size_t)b * CIN * NG;
        #pragma unroll 1
        for (int g = lane; g < NG; g += 32) {
            float gv = fmaf((float)g, step, xmin);
            float dd0 = gv - xv0, dd1 = gv - xv1;
            float d20 = dd0 * dd0, d21 = dd1 * dd1;
            #pragma unroll
            for (int c = 0; c < CIN; c++) {
                float rv = rb[c * NG + g];
                a0[c] = fmaf(rv, ex2(d20 * kneg[c]), a0[c]);
                a1[c] = fmaf(rv, ex2(d21 * kneg[c]), a1[c]);
            }
        }
        #pragma unroll
        for (int s = 16; s > 0; s >>= 1)
            #pragma unroll
            for (int c = 0; c < CIN; c++) {
                a0[c] += __shfl_xor_sync(0xFFFFFFFFu, a0[c], s);
                a1[c] += __shfl_xor_sync(0xFFFFFFFFu, a1[c], s);
            }
        float o0v = bv, o1v = bv;
        #pragma unroll
        for (int c = 0; c < CIN; c++) {
            o0v = fmaf(a0[c], W_s[c * COUT + lane], o0v);
            o1v = fmaf(a1[c], W_s[c * COUT + lane], o1v);
        }
        out[((size_t)b * NOUT + o0 + 0) * COUT + lane] = o0v;
        out[((size_t)b * NOUT + o0 + 1) * COUT + lane] = o1v;
    }
}

extern "C" void kernel_launch(void* const* d_in, const int* in_sizes, int n_in,
                              void* d_out, int out_size) {
    const float* r     = (const float*)d_in[0];
    const float* xc    = (const float*)d_in[1];
    // d_in[2] = y_context — unused by the reference computation.
    const float* xt    = (const float*)d_in[3];
    const float* sigma = (const float*)d_in[4];
    const float* W     = (const float*)d_in[5];
    const float* bias  = (const float*)d_in[6];
    float* out = (float*)d_out;

    (void)in_sizes; (void)n_in; (void)out_size;

    const int smem_bytes = KSPLIT * FREG * 4          // r fp32 (139.3 KB)
                         + CIN * COUT * 4             // W (2 KB)
                         + KSPLIT * 32 * ZROW * 4;    // z partials (41 KB)
    cudaFuncSetAttribute(conv_decoder_mma,
                         cudaFuncAttributeMaxDynamicSharedMemorySize, smem_bytes);

    dim3 grid(NOUT / 32, NB);   // (32, 4) = 128 blocks, 1 per SM
    conv_decoder_mma<<<grid, TPB, smem_bytes>>>(r, xc, xt, sigma, W, bias, out);
}